// round 13
// baseline (speedup 1.0000x reference)
#include <cuda_runtime.h>
#include <cstdint>
#include <cstddef>

// STPCell fused kernel, R11: persistent work-list (592 CTAs, unit = (j, 8
// batches)), TMA bulk (cp.async.bulk) producer ring: one thread refills a
// 4KB+4KB slot the moment it frees (mbarrier full/empty pairs, ND=4).
// With 8 seqs/unit = 2*ND, all wait parities are compile-time constants.
// px folded per-unit; single kernel launch.

#define HH    1024
#define IND   512
#define BB    32
#define NCTA  592                      // 4 per SM * 148 SMs
#define NUNIT 4096                     // 1024 j * 4 b-groups
#define BPU   8                        // batches per unit
#define ND    4                        // ring slots (= prefetch distance)
#define BSTR  ((size_t)HH * HH * 4)    // bytes between batches of X/U

__device__ __forceinline__ float sigf(float v) {
    return 1.0f / (1.0f + __expf(-v));
}

__device__ __forceinline__ uint32_t smem_u32(const void* p) {
    return (uint32_t)__cvta_generic_to_shared(p);
}
__device__ __forceinline__ void mbar_init(uint32_t a, uint32_t cnt) {
    asm volatile("mbarrier.init.shared.b64 [%0], %1;" :: "r"(a), "r"(cnt) : "memory");
}
__device__ __forceinline__ void mbar_arrive(uint32_t a) {
    asm volatile("mbarrier.arrive.shared.b64 _, [%0];" :: "r"(a) : "memory");
}
__device__ __forceinline__ void mbar_expect_tx(uint32_t a, uint32_t bytes) {
    asm volatile("mbarrier.arrive.expect_tx.shared.b64 _, [%0], %1;"
                 :: "r"(a), "r"(bytes) : "memory");
}
__device__ __forceinline__ void mbar_wait(uint32_t a, uint32_t parity) {
    asm volatile(
        "{\n\t.reg .pred P;\n\t"
        "WL_%=:\n\t"
        "mbarrier.try_wait.parity.acquire.cta.shared::cta.b64 P, [%0], %1, 0x989680;\n\t"
        "@P bra.uni WD_%=;\n\t"
        "bra.uni WL_%=;\n\t"
        "WD_%=:\n\t}"
        :: "r"(a), "r"(parity) : "memory");
}
__device__ __forceinline__ void tma_bulk4k(uint32_t dst, const void* src, uint32_t mbar) {
    asm volatile(
        "cp.async.bulk.shared::cta.global.mbarrier::complete_tx::bytes [%0], [%1], %2, [%3];"
        :: "r"(dst), "l"(src), "r"(4096u), "r"(mbar) : "memory");
}

__global__ __launch_bounds__(256, 4) void stp_main(
    const float* __restrict__ x_in,   // (IN, B)
    const float* __restrict__ h,      // (B, H)
    const float* __restrict__ X,      // (B, H, H)
    const float* __restrict__ U,      // (B, H, H)
    const float* __restrict__ c_x,    // (H, H)
    const float* __restrict__ c_u,    // (H, H)
    const float* __restrict__ c_U,    // (H, H)
    const float* __restrict__ c_h,    // (H, 1)
    const float* __restrict__ w,      // (H, H)
    const float* __restrict__ p,      // (H, IN)
    const float* __restrict__ bias,   // (H, 1)
    float* __restrict__ out)          // (B, H)
{
    const int cta  = blockIdx.x;
    const int tid  = threadIdx.x;
    const int lane = tid & 31;
    const int warp = tid >> 5;

    // ring: slot = 8KB (4KB X row + 4KB U row)
    __shared__ alignas(1024) float4 stg[ND][512];   // 32 KB
    __shared__ uint64_t fullb[ND], emptyb[ND];
    __shared__ float sbuf[32][BPU];                 // px partials (1 KB)
    __shared__ float sred[8][BPU];
    __shared__ float px_s[BPU];
    __shared__ float hj_s[BPU];

    const uint32_t full0  = smem_u32(&fullb[0]);
    const uint32_t empty0 = smem_u32(&emptyb[0]);
    const uint32_t stg0   = smem_u32(&stg[0][0]);

    const float4* __restrict__ h4 = reinterpret_cast<const float4*>(h);
    const char* Xc = reinterpret_cast<const char*>(X);
    const char* Uc = reinterpret_cast<const char*>(U);

    if (tid == 0) {
        #pragma unroll
        for (int s = 0; s < ND; ++s) {
            mbar_init(full0  + s * 8, 1);   // 1 arrive (expect_tx) + tx bytes
            mbar_init(empty0 + s * 8, 8);   // one elected arrive per warp
        }
        asm volatile("fence.proxy.async.shared::cta;" ::: "memory");
    }
    __syncthreads();

    const int T = (NUNIT - 1 - cta) / NCTA + 1;    // 6 or 7 units
    int j  = cta >> 2;
    int bb = (cta & 3) * BPU;
    size_t cur = (size_t)bb * BSTR + (size_t)j * 4096;   // byte base of unit rows

    // prologue: fill slots with seq 0..3 (batches bb..bb+3)
    if (tid == 0) {
        #pragma unroll
        for (int s = 0; s < ND; ++s) {
            mbar_expect_tx(full0 + s * 8, 8192);
            tma_bulk4k(stg0 + s * 8192,        Xc + cur + (size_t)s * BSTR, full0 + s * 8);
            tma_bulk4k(stg0 + s * 8192 + 4096, Uc + cur + (size_t)s * BSTR, full0 + s * 8);
        }
    }

    // ================= unit loop =================
    #pragma unroll 1
    for (int t = 0; t < T; ++t) {
        int jn = j, bbn = bb;
        if (t + 1 < T) {
            const int un = cta + (t + 1) * NCTA;
            jn  = un >> 2;
            bbn = (un & 3) * BPU;
        }
        const size_t nxt = (size_t)bbn * BSTR + (size_t)jn * 4096;

        __syncthreads();               // prior unit's smem (sred/px_s/hj_s) done

        // ---- per-unit constants ----
        const int rowP = j * (HH / 4) + tid;
        const float4 cxv = __ldg(reinterpret_cast<const float4*>(c_x) + rowP);
        const float4 cuv = __ldg(reinterpret_cast<const float4*>(c_u) + rowP);
        const float4 cUv = __ldg(reinterpret_cast<const float4*>(c_U) + rowP);
        const float4 wv  = __ldg(reinterpret_cast<const float4*>(w)   + rowP);

        if (tid < BPU) hj_s[tid] = h[(bb + tid) * HH + j];

        // px partials: 32 segments of 16 i, b = tid & 7
        {
            const int seg = tid >> 3;
            const int bl  = tid & 7;
            const float* prow = p + j * IND;
            float a = 0.0f;
            #pragma unroll 8
            for (int i = seg * 16; i < seg * 16 + 16; ++i)
                a = fmaf(prow[i], x_in[i * BB + bb + bl], a);
            sbuf[seg][bl] = a;
        }
        __syncthreads();
        if (tid < BPU) {
            float s = 0.0f;
            #pragma unroll
            for (int q = 0; q < 32; ++q) s += sbuf[q][tid];
            px_s[tid] = s;
        }

        float4 zx, zu, uc;
        zx.x = 0.001f + 0.099f * sigf(cxv.x);
        zx.y = 0.001f + 0.099f * sigf(cxv.y);
        zx.z = 0.001f + 0.099f * sigf(cxv.z);
        zx.w = 0.001f + 0.099f * sigf(cxv.w);
        zu.x = 0.001f + 0.099f * sigf(cuv.x);
        zu.y = 0.001f + 0.099f * sigf(cuv.y);
        zu.z = 0.001f + 0.099f * sigf(cuv.z);
        zu.w = 0.001f + 0.099f * sigf(cuv.w);
        uc.x = 0.9f * sigf(cUv.x);
        uc.y = 0.9f * sigf(cUv.y);
        uc.z = 0.9f * sigf(cUv.z);
        uc.w = 0.9f * sigf(cUv.w);

        __syncthreads();               // hj_s published (px_s read only in epi)

        // ---- 8 seqs: 2 groups of 4; slot = q&3, parity = (q>>2)&1 ----
        #pragma unroll
        for (int g = 0; g < 2; ++g) {
            float a[4] = {0.0f, 0.0f, 0.0f, 0.0f};

            #pragma unroll
            for (int qq = 0; qq < 4; ++qq) {
                const int q      = g * 4 + qq;       // compile-time
                const int slot   = q & 3;
                const uint32_t par = (uint32_t)((q >> 2) & 1);

                mbar_wait(full0 + slot * 8, par);
                const float4 x0 = stg[slot][tid];
                const float4 u0 = stg[slot][256 + tid];

                const float4 hv = __ldg(h4 + (bb + q) * (HH / 4) + tid);
                const float  hj = hj_s[q];

                // X_new = fma(z_x, 1-X, X) - U*(X*hj)
                // U_new = Ucap*(z_u+hj) + U*((1-z_u)-Ucap*hj), clip [Ucap,1]
                // a[qq] += (w * U_new * X_new) * h[b,k]
                #define STP_PROC(C)                                         \
                {                                                           \
                    float xx = x0.C, uu = u0.C;                             \
                    float xnew = fmaf(zx.C, 1.0f - xx, xx);                 \
                    xnew = fmaf(-uu, xx * hj, xnew);                        \
                    float addu = uc.C * (zu.C + hj);                        \
                    float cofu = fmaf(-uc.C, hj, 1.0f - zu.C);              \
                    float unew = fmaf(uu, cofu, addu);                      \
                    unew = fminf(fmaxf(unew, uc.C), 1.0f);                 \
                    a[qq] = fmaf(wv.C * unew * xnew, hv.C, a[qq]);          \
                }
                STP_PROC(x) STP_PROC(y) STP_PROC(z) STP_PROC(w)
                #undef STP_PROC

                // release the slot: one arrive per warp after its reads
                __syncwarp();
                if (lane == 0) mbar_arrive(empty0 + slot * 8);

                // producer: refill this slot with seq q+4 the moment it's empty
                if (tid == 0) {
                    mbar_wait(empty0 + slot * 8, par);
                    if (q < 4 || t + 1 < T) {
                        const size_t srcoff = (q < 4)
                            ? cur + (size_t)(q + 4) * BSTR
                            : nxt + (size_t)(q - 4) * BSTR;
                        mbar_expect_tx(full0 + slot * 8, 8192);
                        tma_bulk4k(stg0 + slot * 8192,        Xc + srcoff, full0 + slot * 8);
                        tma_bulk4k(stg0 + slot * 8192 + 4096, Uc + srcoff, full0 + slot * 8);
                    }
                }
            }

            // 4 interleaved shuffle trees
            #pragma unroll
            for (int o = 16; o > 0; o >>= 1) {
                a[0] += __shfl_xor_sync(0xffffffffu, a[0], o);
                a[1] += __shfl_xor_sync(0xffffffffu, a[1], o);
                a[2] += __shfl_xor_sync(0xffffffffu, a[2], o);
                a[3] += __shfl_xor_sync(0xffffffffu, a[3], o);
            }
            if (lane == 0) {
                sred[warp][g * 4 + 0] = a[0];
                sred[warp][g * 4 + 1] = a[1];
                sred[warp][g * 4 + 2] = a[2];
                sred[warp][g * 4 + 3] = a[3];
            }
        }
        __syncthreads();

        // ---- finalize: thread q (< 8) writes out[bb+q, j] ----
        if (tid < BPU) {
            float rec = 0.0f;
            #pragma unroll
            for (int q = 0; q < 8; ++q) rec += sred[q][tid];

            float pre = rec + px_s[tid] + __ldg(bias + j);
            float zh  = 0.5f * sigf(__ldg(c_h + j));      // E_H = 0.5
            float hbj = hj_s[tid];                        // == h[b*HH + j]
            out[(bb + tid) * HH + j] = fmaf(zh, sigf(pre) - hbj, hbj);
        }

        j = jn; bb = bbn; cur = nxt;
    }
}

// ---------------------------------------------------------------------------
// Inputs (metadata order): x, h, X, U, c_x, c_u, c_U, c_h, w, p, b
// ---------------------------------------------------------------------------
extern "C" void kernel_launch(void* const* d_in, const int* in_sizes, int n_in,
                              void* d_out, int out_size)
{
    const float* x_in = (const float*)d_in[0];
    const float* h    = (const float*)d_in[1];
    const float* X    = (const float*)d_in[2];
    const float* U    = (const float*)d_in[3];
    const float* c_x  = (const float*)d_in[4];
    const float* c_u  = (const float*)d_in[5];
    const float* c_U  = (const float*)d_in[6];
    const float* c_h  = (const float*)d_in[7];
    const float* w    = (const float*)d_in[8];
    const float* p    = (const float*)d_in[9];
    const float* bias = (const float*)d_in[10];
    float* out = (float*)d_out;

    stp_main<<<NCTA, 256>>>(x_in, h, X, U, c_x, c_u, c_U, c_h, w, p, bias, out);
}

// round 14
// speedup vs baseline: 1.0828x; 1.0828x over previous
#include <cuda_runtime.h>
#include <cstdint>
#include <cstddef>

// STPCell fused kernel, R13: warp-specialized producer/consumer.
// CTA = 288 threads: warps 0-7 consume (256 threads = one 1024-float row),
// warp 8 is a dedicated TMA-bulk producer that streams X/U rows through a
// 4-slot x 8KB smem ring. Producer waits never block consumers (and vice
// versa), keeping the DRAM request queue continuously fed.
// Grid = 1024 CTAs (one j each, all 32 batches). All mbarrier parities are
// compile-time constants (32 seqs = 8 uses x 4 slots, fully unrolled).

#define HH    1024
#define IND   512
#define BB    32
#define ND    4                        // ring slots
#define BSTR  ((size_t)HH * HH * 4)    // bytes between batches of X/U

__device__ __forceinline__ float sigf(float v) {
    return 1.0f / (1.0f + __expf(-v));
}

__device__ __forceinline__ uint32_t smem_u32(const void* p) {
    return (uint32_t)__cvta_generic_to_shared(p);
}
__device__ __forceinline__ void mbar_init(uint32_t a, uint32_t cnt) {
    asm volatile("mbarrier.init.shared.b64 [%0], %1;" :: "r"(a), "r"(cnt) : "memory");
}
__device__ __forceinline__ void mbar_arrive(uint32_t a) {
    asm volatile("mbarrier.arrive.shared.b64 _, [%0];" :: "r"(a) : "memory");
}
__device__ __forceinline__ void mbar_expect_tx(uint32_t a, uint32_t bytes) {
    asm volatile("mbarrier.arrive.expect_tx.shared.b64 _, [%0], %1;"
                 :: "r"(a), "r"(bytes) : "memory");
}
__device__ __forceinline__ void mbar_wait(uint32_t a, uint32_t parity) {
    asm volatile(
        "{\n\t.reg .pred P;\n\t"
        "WL_%=:\n\t"
        "mbarrier.try_wait.parity.acquire.cta.shared::cta.b64 P, [%0], %1, 0x989680;\n\t"
        "@P bra.uni WD_%=;\n\t"
        "bra.uni WL_%=;\n\t"
        "WD_%=:\n\t}"
        :: "r"(a), "r"(parity) : "memory");
}
__device__ __forceinline__ void tma_bulk4k(uint32_t dst, const void* src, uint32_t mbar) {
    asm volatile(
        "cp.async.bulk.shared::cta.global.mbarrier::complete_tx::bytes [%0], [%1], %2, [%3];"
        :: "r"(dst), "l"(src), "r"(4096u), "r"(mbar) : "memory");
}

__global__ __launch_bounds__(288, 3) void stp_main(
    const float* __restrict__ x_in,   // (IN, B)
    const float* __restrict__ h,      // (B, H)
    const float* __restrict__ X,      // (B, H, H)
    const float* __restrict__ U,      // (B, H, H)
    const float* __restrict__ c_x,    // (H, H)
    const float* __restrict__ c_u,    // (H, H)
    const float* __restrict__ c_U,    // (H, H)
    const float* __restrict__ c_h,    // (H, 1)
    const float* __restrict__ w,      // (H, H)
    const float* __restrict__ p,      // (H, IN)
    const float* __restrict__ bias,   // (H, 1)
    float* __restrict__ out)          // (B, H)
{
    const int j    = blockIdx.x;
    const int tid  = threadIdx.x;
    const int lane = tid & 31;
    const int warp = tid >> 5;                 // 0..7 consumers, 8 producer

    __shared__ alignas(1024) float4 stg[ND][512];   // 32 KB ring (4KB X + 4KB U per slot)
    __shared__ uint64_t fullb[ND], emptyb[ND];
    __shared__ float sred[8][BB];              // px partials, then dot partials
    __shared__ float px_s[BB];
    __shared__ float hj_s[BB];

    const uint32_t full0  = smem_u32(&fullb[0]);
    const uint32_t empty0 = smem_u32(&emptyb[0]);
    const uint32_t stg0   = smem_u32(&stg[0][0]);

    if (tid == 0) {
        #pragma unroll
        for (int s = 0; s < ND; ++s) {
            mbar_init(full0  + s * 8, 1);      // expect_tx arrive (+ tx bytes)
            mbar_init(empty0 + s * 8, 8);      // one arrive per consumer warp
        }
        asm volatile("fence.proxy.async.shared::cta;" ::: "memory");
    }
    __syncthreads();   // the ONLY full-CTA barrier; producer detaches after this

    // ======================= producer warp =======================
    if (warp == 8) {
        if (lane == 0) {
            const char* Xg = reinterpret_cast<const char*>(X) + (size_t)j * 4096;
            const char* Ug = reinterpret_cast<const char*>(U) + (size_t)j * 4096;
            #pragma unroll 1
            for (int g = 0; g < 8; ++g) {          // use #g of each slot
                #pragma unroll
                for (int sl = 0; sl < ND; ++sl) {
                    const int s = g * 4 + sl;       // seq = batch index
                    if (g > 0) mbar_wait(empty0 + sl * 8, (uint32_t)((g - 1) & 1));
                    mbar_expect_tx(full0 + sl * 8, 8192);
                    tma_bulk4k(stg0 + sl * 8192,        Xg + (size_t)s * BSTR, full0 + sl * 8);
                    tma_bulk4k(stg0 + sl * 8192 + 4096, Ug + (size_t)s * BSTR, full0 + sl * 8);
                }
            }
        }
        return;   // producer done (all its TMAs are consumed before CTA exit)
    }

    // ======================= consumer warps (tid < 256) =======================
    const int rowP = j * (HH / 4) + tid;
    const float4* __restrict__ h4 = reinterpret_cast<const float4*>(h);

    // per-(j,k) constants
    const float4 cxv = __ldg(reinterpret_cast<const float4*>(c_x) + rowP);
    const float4 cuv = __ldg(reinterpret_cast<const float4*>(c_u) + rowP);
    const float4 cUv = __ldg(reinterpret_cast<const float4*>(c_U) + rowP);
    const float4 wv  = __ldg(reinterpret_cast<const float4*>(w)   + rowP);

    if (tid < BB) hj_s[tid] = h[tid * HH + j];

    // (p @ x)[j, 0..31]: 8 segments of 64 i, b = lane
    {
        const int b   = tid & 31;
        const int seg = tid >> 5;
        const float* prow = p + j * IND;
        float a = 0.0f;
        #pragma unroll 8
        for (int i = seg * 64; i < seg * 64 + 64; ++i)
            a = fmaf(prow[i], x_in[i * BB + b], a);
        sred[seg][b] = a;
    }
    asm volatile("bar.sync 1, 256;" ::: "memory");   // consumer-only barrier
    if (tid < BB) {
        float s = 0.0f;
        #pragma unroll
        for (int q = 0; q < 8; ++q) s += sred[q][tid];
        px_s[tid] = s;
    }

    float4 zx, zu, uc;
    zx.x = 0.001f + 0.099f * sigf(cxv.x);
    zx.y = 0.001f + 0.099f * sigf(cxv.y);
    zx.z = 0.001f + 0.099f * sigf(cxv.z);
    zx.w = 0.001f + 0.099f * sigf(cxv.w);
    zu.x = 0.001f + 0.099f * sigf(cuv.x);
    zu.y = 0.001f + 0.099f * sigf(cuv.y);
    zu.z = 0.001f + 0.099f * sigf(cuv.z);
    zu.w = 0.001f + 0.099f * sigf(cuv.w);
    uc.x = 0.9f * sigf(cUv.x);
    uc.y = 0.9f * sigf(cUv.y);
    uc.z = 0.9f * sigf(cUv.z);
    uc.w = 0.9f * sigf(cUv.w);

    asm volatile("bar.sync 1, 256;" ::: "memory");   // hj_s/px_s published; sred free

    // ---- 32 batches: 8 groups of 4; slot = s&3, full parity = g&1 ----
    #pragma unroll 1
    for (int g = 0; g < 8; ++g) {
        float a[4] = {0.0f, 0.0f, 0.0f, 0.0f};
        const uint32_t par = (uint32_t)(g & 1);

        #pragma unroll
        for (int qq = 0; qq < 4; ++qq) {
            const int s = g * 4 + qq;

            mbar_wait(full0 + qq * 8, par);
            const float4 x0 = stg[qq][tid];
            const float4 u0 = stg[qq][256 + tid];

            const float4 hv = __ldg(h4 + s * (HH / 4) + tid);
            const float  hj = hj_s[s];

            // X_new = fma(z_x, 1-X, X) - U*(X*hj)
            // U_new = Ucap*(z_u+hj) + U*((1-z_u)-Ucap*hj), clip [Ucap,1]
            // a[qq] += (w * U_new * X_new) * h[b,k]
            #define STP_PROC(C)                                             \
            {                                                               \
                float xx = x0.C, uu = u0.C;                                 \
                float xnew = fmaf(zx.C, 1.0f - xx, xx);                     \
                xnew = fmaf(-uu, xx * hj, xnew);                            \
                float addu = uc.C * (zu.C + hj);                            \
                float cofu = fmaf(-uc.C, hj, 1.0f - zu.C);                  \
                float unew = fmaf(uu, cofu, addu);                          \
                unew = fminf(fmaxf(unew, uc.C), 1.0f);                     \
                a[qq] = fmaf(wv.C * unew * xnew, hv.C, a[qq]);              \
            }
            STP_PROC(x) STP_PROC(y) STP_PROC(z) STP_PROC(w)
            #undef STP_PROC

            __syncwarp();
            if (lane == 0) mbar_arrive(empty0 + qq * 8);
        }

        // 4 interleaved shuffle trees (producer keeps streaming meanwhile)
        #pragma unroll
        for (int o = 16; o > 0; o >>= 1) {
            a[0] += __shfl_xor_sync(0xffffffffu, a[0], o);
            a[1] += __shfl_xor_sync(0xffffffffu, a[1], o);
            a[2] += __shfl_xor_sync(0xffffffffu, a[2], o);
            a[3] += __shfl_xor_sync(0xffffffffu, a[3], o);
        }
        if (lane == 0) {
            sred[warp][g * 4 + 0] = a[0];
            sred[warp][g * 4 + 1] = a[1];
            sred[warp][g * 4 + 2] = a[2];
            sred[warp][g * 4 + 3] = a[3];
        }
    }
    asm volatile("bar.sync 1, 256;" ::: "memory");

    // ---- finalize: thread b (< 32) writes out[b, j] ----
    if (tid < BB) {
        const int b = tid;
        float rec = 0.0f;
        #pragma unroll
        for (int q = 0; q < 8; ++q) rec += sred[q][b];

        float pre = rec + px_s[b] + __ldg(bias + j);
        float zh  = 0.5f * sigf(__ldg(c_h + j));      // E_H = 0.5
        float hbj = hj_s[b];                          // == h[b*HH + j]
        out[b * HH + j] = fmaf(zh, sigf(pre) - hbj, hbj);
    }
}

// ---------------------------------------------------------------------------
// Inputs (metadata order): x, h, X, U, c_x, c_u, c_U, c_h, w, p, b
// ---------------------------------------------------------------------------
extern "C" void kernel_launch(void* const* d_in, const int* in_sizes, int n_in,
                              void* d_out, int out_size)
{
    const float* x_in = (const float*)d_in[0];
    const float* h    = (const float*)d_in[1];
    const float* X    = (const float*)d_in[2];
    const float* U    = (const float*)d_in[3];
    const float* c_x  = (const float*)d_in[4];
    const float* c_u  = (const float*)d_in[5];
    const float* c_U  = (const float*)d_in[6];
    const float* c_h  = (const float*)d_in[7];
    const float* w    = (const float*)d_in[8];
    const float* p    = (const float*)d_in[9];
    const float* bias = (const float*)d_in[10];
    float* out = (float*)d_out;

    stp_main<<<HH, 288>>>(x_in, h, X, U, c_x, c_u, c_U, c_h, w, p, bias, out);
}

// round 15
// speedup vs baseline: 1.2141x; 1.1213x over previous
#include <cuda_runtime.h>
#include <cstdint>
#include <cstddef>

// STPCell fused kernel, R14: persistent work-list (592 CTAs, unit = (j, 8
// batches), 1.2% tail), static cp.async ring (ND=4, proven in R8), inline
// per-unit px, and packed f32x2 (FFMA2) inner math: streamed data consumed as
// pre-packed ulonglong2 pairs, ~40% fewer hot-loop instructions.

#define HH    1024
#define IND   512
#define BB    32
#define NCTA  592                      // 4 per SM * 148 SMs
#define NUNIT 4096                     // 1024 j * 4 b-groups
#define BPU   8                        // batches per unit
#define ND    4                        // ring stages == prefetch distance
#define BSTR  ((size_t)HH * HH * 4)    // bytes between batches of X/U

typedef unsigned long long ull;

__device__ __forceinline__ float sigf(float v) {
    return 1.0f / (1.0f + __expf(-v));
}

// ---- f32x2 packed helpers ----
__device__ __forceinline__ ull pk2(float lo, float hi) {
    ull r;
    asm("mov.b64 %0, {%1, %2};" : "=l"(r)
        : "r"(__float_as_uint(lo)), "r"(__float_as_uint(hi)));
    return r;
}
__device__ __forceinline__ void upk2(float& lo, float& hi, ull v) {
    unsigned int a, b;
    asm("mov.b64 {%0, %1}, %2;" : "=r"(a), "=r"(b) : "l"(v));
    lo = __uint_as_float(a); hi = __uint_as_float(b);
}
__device__ __forceinline__ ull fma2(ull a, ull b, ull c) {
    ull d;
    asm("fma.rn.f32x2 %0, %1, %2, %3;" : "=l"(d) : "l"(a), "l"(b), "l"(c));
    return d;
}
__device__ __forceinline__ ull mul2(ull a, ull b) {
    ull d;
    asm("mul.rn.f32x2 %0, %1, %2;" : "=l"(d) : "l"(a), "l"(b));
    return d;
}

__device__ __forceinline__ void cp16(uint32_t saddr, const void* gaddr) {
    asm volatile("cp.async.cg.shared.global [%0], [%1], 16;\n"
                 :: "r"(saddr), "l"(gaddr));
}
#define CP_COMMIT() asm volatile("cp.async.commit_group;\n" ::: "memory")
#define CP_WAIT(n)  asm volatile("cp.async.wait_group %0;\n" :: "n"(n) : "memory")

__global__ __launch_bounds__(256, 4) void stp_main(
    const float* __restrict__ x_in,   // (IN, B)
    const float* __restrict__ h,      // (B, H)
    const float* __restrict__ X,      // (B, H, H)
    const float* __restrict__ U,      // (B, H, H)
    const float* __restrict__ c_x,    // (H, H)
    const float* __restrict__ c_u,    // (H, H)
    const float* __restrict__ c_U,    // (H, H)
    const float* __restrict__ c_h,    // (H, 1)
    const float* __restrict__ w,      // (H, H)
    const float* __restrict__ p,      // (H, IN)
    const float* __restrict__ bias,   // (H, 1)
    float* __restrict__ out)          // (B, H)
{
    const int cta  = blockIdx.x;
    const int tid  = threadIdx.x;
    const int lane = tid & 31;
    const int warp = tid >> 5;

    __shared__ alignas(1024) ulonglong2 stg[ND][512];  // slot: [0..255]=X row, [256..511]=U row
    __shared__ float sbuf[32][BPU];                    // px partials
    __shared__ float sred[8][BPU];                     // dot partials
    __shared__ float px_s[BPU];
    __shared__ float hj_s[BPU];

    const ulonglong2* __restrict__ h2 = reinterpret_cast<const ulonglong2*>(h);
    const char* Xc = reinterpret_cast<const char*>(X);
    const char* Uc = reinterpret_cast<const char*>(U);
    const uint32_t xs0 = (uint32_t)__cvta_generic_to_shared(&stg[0][tid]);

    const int T = (NUNIT - 1 - cta) / NCTA + 1;        // 6 or 7 units
    int j  = cta >> 2;
    int bb = (cta & 3) * BPU;
    size_t cur = (size_t)bb * BSTR + (size_t)j * 4096 + (size_t)tid * 16;

    // prologue: fill ring with seq 0..3 (batches bb..bb+3)
    #pragma unroll
    for (int s = 0; s < ND; ++s) {
        cp16(xs0 + s * 8192,        Xc + cur + (size_t)s * BSTR);
        cp16(xs0 + s * 8192 + 4096, Uc + cur + (size_t)s * BSTR);
        CP_COMMIT();
    }

    // ================= unit loop =================
    #pragma unroll 1
    for (int t = 0; t < T; ++t) {
        int jn = j, bbn = bb;
        if (t + 1 < T) {
            const int un = cta + (t + 1) * NCTA;
            jn  = un >> 2;
            bbn = (un & 3) * BPU;
        }
        const size_t nxt = (size_t)bbn * BSTR + (size_t)jn * 4096 + (size_t)tid * 16;

        // ---- per-unit constants (L2-shared with 3 sibling CTAs of this j) ----
        const int rowP = j * (HH / 4) + tid;
        const float4 cxv = __ldg(reinterpret_cast<const float4*>(c_x) + rowP);
        const float4 cuv = __ldg(reinterpret_cast<const float4*>(c_u) + rowP);
        const float4 cUv = __ldg(reinterpret_cast<const float4*>(c_U) + rowP);
        const float4 wv  = __ldg(reinterpret_cast<const float4*>(w)   + rowP);

        if (tid < BPU) hj_s[tid] = h[(bb + tid) * HH + j];

        // px partials: 32 segments of 16 i, b = tid & 7
        {
            const int seg = tid >> 3;
            const int bl  = tid & 7;
            const float* prow = p + j * IND;
            float a = 0.0f;
            #pragma unroll 8
            for (int i = seg * 16; i < seg * 16 + 16; ++i)
                a = fmaf(prow[i], x_in[i * BB + bb + bl], a);
            sbuf[seg][bl] = a;
        }

        // packed per-(j,k) constants
        float zx0 = 0.001f + 0.099f * sigf(cxv.x), zx1 = 0.001f + 0.099f * sigf(cxv.y);
        float zx2_ = 0.001f + 0.099f * sigf(cxv.z), zx3 = 0.001f + 0.099f * sigf(cxv.w);
        float zu0 = 0.001f + 0.099f * sigf(cuv.x), zu1 = 0.001f + 0.099f * sigf(cuv.y);
        float zu2_ = 0.001f + 0.099f * sigf(cuv.z), zu3 = 0.001f + 0.099f * sigf(cuv.w);
        float uca = 0.9f * sigf(cUv.x), ucb = 0.9f * sigf(cUv.y);
        float ucc = 0.9f * sigf(cUv.z), ucd = 0.9f * sigf(cUv.w);

        ull zx2[2], c12[2], uc2[2], B02[2], B12[2], w2[2];
        zx2[0] = pk2(zx0, zx1);             zx2[1] = pk2(zx2_, zx3);
        c12[0] = pk2(1.f - zx0, 1.f - zx1); c12[1] = pk2(1.f - zx2_, 1.f - zx3);
        uc2[0] = pk2(uca, ucb);             uc2[1] = pk2(ucc, ucd);
        B02[0] = pk2(uca * zu0, ucb * zu1); B02[1] = pk2(ucc * zu2_, ucd * zu3);
        B12[0] = pk2(1.f - zu0, 1.f - zu1); B12[1] = pk2(1.f - zu2_, 1.f - zu3);
        w2[0]  = pk2(wv.x, wv.y);           w2[1]  = pk2(wv.z, wv.w);

        __syncthreads();                    // sync1: hj_s/sbuf published
        if (tid < BPU) {
            float s = 0.0f;
            #pragma unroll
            for (int q = 0; q < 32; ++q) s += sbuf[q][tid];
            px_s[tid] = s;
        }

        // ---- 8 seqs: 2 groups of 4, static ring (slot = q&3) ----
        #pragma unroll
        for (int g = 0; g < 2; ++g) {
            ull acc2[4] = {0ull, 0ull, 0ull, 0ull};

            #pragma unroll
            for (int qq = 0; qq < 4; ++qq) {
                const int q = g * 4 + qq;   // compile-time

                CP_WAIT(3);
                const ulonglong2 xq = stg[q & 3][tid];
                const ulonglong2 uq = stg[q & 3][256 + tid];

                // refill slot with seq q+4 (next unit for q>=4; last unit self-refetch)
                {
                    const size_t adr = (q < 4)
                        ? cur + (size_t)(q + 4) * BSTR
                        : nxt + (size_t)(q - 4) * BSTR;
                    cp16(xs0 + (q & 3) * 8192,        Xc + adr);
                    cp16(xs0 + (q & 3) * 8192 + 4096, Uc + adr);
                    CP_COMMIT();
                }

                const ulonglong2 hq = h2[(size_t)(bb + q) * 256 + tid];
                const float hj  = hj_s[q];
                const ull hj2   = pk2(hj, hj);
                const ull nhj2  = pk2(-hj, -hj);

                // packed: xnew = fma(x, (1-zx) - u*hj, zx)
                //         unew = fma(u, (1-zu) - uc*hj, uc*zu + uc*hj), clip [uc,1]
                //         acc += w * unew * xnew * h
                #define PPAIR(XP, UP, HP, P)                                \
                {                                                           \
                    ull tt  = fma2(UP, nhj2, c12[P]);                       \
                    ull xn  = fma2(XP, tt, zx2[P]);                         \
                    ull adu = fma2(uc2[P], hj2, B02[P]);                    \
                    ull cof = fma2(uc2[P], nhj2, B12[P]);                   \
                    ull un  = fma2(UP, cof, adu);                           \
                    float s0, s1, l0, l1;                                   \
                    upk2(s0, s1, un);                                       \
                    upk2(l0, l1, uc2[P]);                                   \
                    s0 = fminf(fmaxf(s0, l0), 1.0f);                        \
                    s1 = fminf(fmaxf(s1, l1), 1.0f);                        \
                    ull W = mul2(pk2(s0, s1), xn);                          \
                    W = mul2(W, w2[P]);                                     \
                    acc2[qq] = fma2(W, HP, acc2[qq]);                       \
                }
                PPAIR(xq.x, uq.x, hq.x, 0)
                PPAIR(xq.y, uq.y, hq.y, 1)
                #undef PPAIR
            }

            // reduce: unpack pair-accumulators, 4 interleaved shuffle trees
            float a[4];
            #pragma unroll
            for (int i = 0; i < 4; ++i) {
                float lo, hi;
                upk2(lo, hi, acc2[i]);
                a[i] = lo + hi;
            }
            #pragma unroll
            for (int o = 16; o > 0; o >>= 1) {
                a[0] += __shfl_xor_sync(0xffffffffu, a[0], o);
                a[1] += __shfl_xor_sync(0xffffffffu, a[1], o);
                a[2] += __shfl_xor_sync(0xffffffffu, a[2], o);
                a[3] += __shfl_xor_sync(0xffffffffu, a[3], o);
            }
            if (lane == 0) {
                sred[warp][g * 4 + 0] = a[0];
                sred[warp][g * 4 + 1] = a[1];
                sred[warp][g * 4 + 2] = a[2];
                sred[warp][g * 4 + 3] = a[3];
            }
        }
        __syncthreads();                    // sync2: sred published

        // ---- finalize: thread q (< 8) writes out[bb+q, j] ----
        if (tid < BPU) {
            float rec = 0.0f;
            #pragma unroll
            for (int q = 0; q < 8; ++q) rec += sred[q][tid];

            float pre = rec + px_s[tid] + __ldg(bias + j);
            float zh  = 0.5f * sigf(__ldg(c_h + j));      // E_H = 0.5
            float hbj = hj_s[tid];                        // == h[b*HH + j]
            out[(bb + tid) * HH + j] = fmaf(zh, sigf(pre) - hbj, hbj);
        }

        j = jn; bb = bbn; cur = nxt;
    }

    CP_WAIT(0);   // drain tail prefetches
}

// ---------------------------------------------------------------------------
// Inputs (metadata order): x, h, X, U, c_x, c_u, c_U, c_h, w, p, b
// ---------------------------------------------------------------------------
extern "C" void kernel_launch(void* const* d_in, const int* in_sizes, int n_in,
                              void* d_out, int out_size)
{
    const float* x_in = (const float*)d_in[0];
    const float* h    = (const float*)d_in[1];
    const float* X    = (const float*)d_in[2];
    const float* U    = (const float*)d_in[3];
    const float* c_x  = (const float*)d_in[4];
    const float* c_u  = (const float*)d_in[5];
    const float* c_U  = (const float*)d_in[6];
    const float* c_h  = (const float*)d_in[7];
    const float* w    = (const float*)d_in[8];
    const float* p    = (const float*)d_in[9];
    const float* bias = (const float*)d_in[10];
    float* out = (float*)d_out;

    stp_main<<<NCTA, 256>>>(x_in, h, X, U, c_x, c_u, c_U, c_h, w, p, bias, out);
}

// round 17
// speedup vs baseline: 1.2928x; 1.0648x over previous
#include <cuda_runtime.h>
#include <cstdint>
#include <cstddef>

// STPCell fused kernel, R15: j-PAIR persistent work-list.
// 296 CTAs x 512 threads (2 CTAs/SM, 32 warps/SM). Unit = (j-pair, 8 batches);
// 2048 units, 1.2% tail. Each batch visit streams 8KB+8KB CONTIGUOUS (rows
// j0,j1 adjacent in memory) through a barrier-free cp.async ring (ND=4,
// static schedule): half the DRAM streams, double the chunk size vs R8.

#define HH    1024
#define IND   512
#define BB    32
#define NCTA  296                      // 2 per SM * 148 SMs
#define NUNIT 2048                     // 512 j-pairs * 4 b-groups
#define BPU   8                        // batches per unit
#define ND    4                        // ring stages == prefetch distance
#define BSTR  ((size_t)HH * HH * 4)    // bytes between batches of X/U
#define SLOT  16384                    // ring slot bytes: 8KB X + 8KB U

__device__ __forceinline__ float sigf(float v) {
    return 1.0f / (1.0f + __expf(-v));
}

__device__ __forceinline__ void cp16(uint32_t saddr, const void* gaddr) {
    asm volatile("cp.async.cg.shared.global [%0], [%1], 16;\n"
                 :: "r"(saddr), "l"(gaddr));
}
#define CP_COMMIT() asm volatile("cp.async.commit_group;\n" ::: "memory")
#define CP_WAIT(n)  asm volatile("cp.async.wait_group %0;\n" :: "n"(n) : "memory")

__global__ __launch_bounds__(512, 2) void stp_main(
    const float* __restrict__ x_in,   // (IN, B)
    const float* __restrict__ h,      // (B, H)
    const float* __restrict__ X,      // (B, H, H)
    const float* __restrict__ U,      // (B, H, H)
    const float* __restrict__ c_x,    // (H, H)
    const float* __restrict__ c_u,    // (H, H)
    const float* __restrict__ c_U,    // (H, H)
    const float* __restrict__ c_h,    // (H, 1)
    const float* __restrict__ w,      // (H, H)
    const float* __restrict__ p,      // (H, IN)
    const float* __restrict__ bias,   // (H, 1)
    float* __restrict__ out)          // (B, H)
{
    extern __shared__ float4 ring[];          // [ND * 1024] float4 = 64 KB
    __shared__ float sbuf[32][16];            // px partials
    __shared__ float sred[16][BPU];           // dot partials per warp
    __shared__ float px_s[16];                // [jh*8 + b]
    __shared__ float hj_s[16];                // [jh*8 + b]

    const int cta  = blockIdx.x;
    const int tid  = threadIdx.x;
    const int lane = tid & 31;
    const int warp = tid >> 5;                // 0..15
    const int kt   = tid & 255;               // k/4 index within the row
    const int jh   = tid >> 8;                // 0: row j0, 1: row j1

    const float4* __restrict__ h4 = reinterpret_cast<const float4*>(h);
    const char* Xc = reinterpret_cast<const char*>(X);
    const char* Uc = reinterpret_cast<const char*>(U);
    const uint32_t rs0 = (uint32_t)__cvta_generic_to_shared(&ring[0]) + tid * 16u;

    const int T = (NUNIT - 1 - cta) / NCTA + 1;          // 6 or 7 units
    int jp = cta >> 2;                                   // j-pair index
    int bb = (cta & 3) * BPU;

    // byte base of this unit's row-pair for batch bb, at this thread's 16B
    size_t cur = ((size_t)bb * HH + 2 * (size_t)jp) * 4096 + (size_t)tid * 16;

    // prologue: fill ring with seq 0..3 (batches bb..bb+3)
    #pragma unroll
    for (int s = 0; s < ND; ++s) {
        cp16(rs0 + s * SLOT,        Xc + cur + (size_t)s * BSTR);
        cp16(rs0 + s * SLOT + 8192, Uc + cur + (size_t)s * BSTR);
        CP_COMMIT();
    }

    // ================= unit loop =================
    #pragma unroll 1
    for (int t = 0; t < T; ++t) {
        int jpn = jp, bbn = bb;
        if (t + 1 < T) {
            const int un = cta + (t + 1) * NCTA;
            jpn = un >> 2;
            bbn = (un & 3) * BPU;
        }
        const size_t nxt = ((size_t)bbn * HH + 2 * (size_t)jpn) * 4096
                         + (size_t)tid * 16;

        const int j = 2 * jp + jh;                       // this thread's row

        // ---- per-unit constants ----
        const int rowP = j * (HH / 4) + kt;
        const float4 cxv = __ldg(reinterpret_cast<const float4*>(c_x) + rowP);
        const float4 cuv = __ldg(reinterpret_cast<const float4*>(c_u) + rowP);
        const float4 cUv = __ldg(reinterpret_cast<const float4*>(c_U) + rowP);
        const float4 wv  = __ldg(reinterpret_cast<const float4*>(w)   + rowP);

        if (tid < 16) hj_s[tid] = h[(bb + (tid & 7)) * HH + 2 * jp + (tid >> 3)];

        // px partials: 32 segments of 16 i; bl = (jh, b) in tid&15
        {
            const int seg = tid >> 4;
            const int bl  = tid & 15;
            const float* prow = p + (2 * jp + (bl >> 3)) * IND;
            float a = 0.0f;
            #pragma unroll 8
            for (int i = seg * 16; i < seg * 16 + 16; ++i)
                a = fmaf(prow[i], x_in[i * BB + bb + (bl & 7)], a);
            sbuf[seg][bl] = a;
        }

        float4 zx, zu, uc;
        zx.x = 0.001f + 0.099f * sigf(cxv.x);
        zx.y = 0.001f + 0.099f * sigf(cxv.y);
        zx.z = 0.001f + 0.099f * sigf(cxv.z);
        zx.w = 0.001f + 0.099f * sigf(cxv.w);
        zu.x = 0.001f + 0.099f * sigf(cuv.x);
        zu.y = 0.001f + 0.099f * sigf(cuv.y);
        zu.z = 0.001f + 0.099f * sigf(cuv.z);
        zu.w = 0.001f + 0.099f * sigf(cuv.w);
        uc.x = 0.9f * sigf(cUv.x);
        uc.y = 0.9f * sigf(cUv.y);
        uc.z = 0.9f * sigf(cUv.z);
        uc.w = 0.9f * sigf(cUv.w);

        __syncthreads();                 // sync1: hj_s + sbuf published
        if (tid < 16) {
            float s = 0.0f;
            #pragma unroll
            for (int q = 0; q < 32; ++q) s += sbuf[q][tid];
            px_s[tid] = s;
        }

        // ---- 8 seqs: 2 groups of 4, static ring (slot = q&3) ----
        #pragma unroll
        for (int g = 0; g < 2; ++g) {
            float a[4] = {0.0f, 0.0f, 0.0f, 0.0f};

            #pragma unroll
            for (int qq = 0; qq < 4; ++qq) {
                const int q = g * 4 + qq;              // compile-time

                CP_WAIT(3);                            // seq q landed
                const float4 x0 = ring[(q & 3) * 1024 + tid];
                const float4 u0 = ring[(q & 3) * 1024 + 512 + tid];

                // refill slot with seq q+4 (next unit when q>=4)
                {
                    const size_t adr = (q < 4)
                        ? cur + (size_t)(q + 4) * BSTR
                        : nxt + (size_t)(q - 4) * BSTR;
                    cp16(rs0 + (q & 3) * SLOT,        Xc + adr);
                    cp16(rs0 + (q & 3) * SLOT + 8192, Uc + adr);
                    CP_COMMIT();
                }

                const float4 hv = __ldg(h4 + (bb + q) * (HH / 4) + kt);
                const float  hj = hj_s[jh * 8 + q];

                // X_new = fma(z_x, 1-X, X) - U*(X*hj)
                // U_new = Ucap*(z_u+hj) + U*((1-z_u)-Ucap*hj), clip [Ucap,1]
                // a[qq] += (w * U_new * X_new) * h[b,k]
                #define STP_PROC(C)                                         \
                {                                                           \
                    float xx = x0.C, uu = u0.C;                             \
                    float xnew = fmaf(zx.C, 1.0f - xx, xx);                 \
                    xnew = fmaf(-uu, xx * hj, xnew);                        \
                    float addu = uc.C * (zu.C + hj);                        \
                    float cofu = fmaf(-uc.C, hj, 1.0f - zu.C);              \
                    float unew = fmaf(uu, cofu, addu);                      \
                    unew = fminf(fmaxf(unew, uc.C), 1.0f);                 \
                    a[qq] = fmaf(wv.C * unew * xnew, hv.C, a[qq]);          \
                }
                STP_PROC(x) STP_PROC(y) STP_PROC(z) STP_PROC(w)
                #undef STP_PROC
            }

            // 4 interleaved shuffle trees
            #pragma unroll
            for (int o = 16; o > 0; o >>= 1) {
                a[0] += __shfl_xor_sync(0xffffffffu, a[0], o);
                a[1] += __shfl_xor_sync(0xffffffffu, a[1], o);
                a[2] += __shfl_xor_sync(0xffffffffu, a[2], o);
                a[3] += __shfl_xor_sync(0xffffffffu, a[3], o);
            }
            if (lane == 0) {
                sred[warp][g * 4 + 0] = a[0];
                sred[warp][g * 4 + 1] = a[1];
                sred[warp][g * 4 + 2] = a[2];
                sred[warp][g * 4 + 3] = a[3];
            }
        }
        __syncthreads();                 // sync2: sred published

        // ---- finalize: thread (jh2, b) < 16 writes out[bb+b, 2jp+jh2] ----
        if (tid < 16) {
            const int jh2 = tid >> 3;
            const int b   = tid & 7;
            const int j2  = 2 * jp + jh2;
            float rec = 0.0f;
            #pragma unroll
            for (int q = 0; q < 8; ++q) rec += sred[jh2 * 8 + q][b];

            float pre = rec + px_s[tid] + __ldg(bias + j2);
            float zh  = 0.5f * sigf(__ldg(c_h + j2));    // E_H = 0.5
            float hbj = hj_s[tid];                       // == h[(bb+b)*HH + j2]
            out[(bb + b) * HH + j2] = fmaf(zh, sigf(pre) - hbj, hbj);
        }

        jp = jpn; bb = bbn; cur = nxt;
    }

    CP_WAIT(0);   // drain tail prefetches
}

// ---------------------------------------------------------------------------
// Inputs (metadata order): x, h, X, U, c_x, c_u, c_U, c_h, w, p, b
// ---------------------------------------------------------------------------
extern "C" void kernel_launch(void* const* d_in, const int* in_sizes, int n_in,
                              void* d_out, int out_size)
{
    const float* x_in = (const float*)d_in[0];
    const float* h    = (const float*)d_in[1];
    const float* X    = (const float*)d_in[2];
    const float* U    = (const float*)d_in[3];
    const float* c_x  = (const float*)d_in[4];
    const float* c_u  = (const float*)d_in[5];
    const float* c_U  = (const float*)d_in[6];
    const float* c_h  = (const float*)d_in[7];
    const float* w    = (const float*)d_in[8];
    const float* p    = (const float*)d_in[9];
    const float* bias = (const float*)d_in[10];
    float* out = (float*)d_out;

    const int ring_bytes = ND * SLOT;     // 64 KB dynamic smem
    cudaFuncSetAttribute(stp_main, cudaFuncAttributeMaxDynamicSharedMemorySize,
                         ring_bytes);
    stp_main<<<NCTA, 512, ring_bytes>>>(x_in, h, X, U, c_x, c_u, c_U, c_h,
                                        w, p, bias, out);
}